// round 1
// baseline (speedup 1.0000x reference)
#include <cuda_runtime.h>
#include <cstdint>

#define Nn 16384
#define Ee 262144
#define Gg 128

// ---------------- scratch (no allocations allowed) ----------------
__device__ float g_t[Nn * 256];     // transform output
__device__ float g_a[Nn * 256];     // activations / edge logits
__device__ int   g_deg[Nn];
__device__ float g_inv[Nn];
__device__ int   g_ptr[Nn + 1];
__device__ int   g_fill[Nn];
__device__ int   g_src[Ee];
__device__ float g_w[Ee];

typedef unsigned long long ull;

#define FMA2(c, a, b) asm("fma.rn.f32x2 %0, %1, %2, %0;" : "+l"(c) : "l"(a), "l"(b))
#define DUP2(o, x)    asm("mov.b64 %0, {%1, %1};" : "=l"(o) : "f"(x))
#define PK2(o, x, y)  asm("mov.b64 %0, {%1, %2};" : "=l"(o) : "f"(x), "f"(y))
#define UPK2(x, y, c) asm("mov.b64 {%0, %1}, %2;" : "=f"(x), "=f"(y) : "l"(c))

__device__ __forceinline__ float sigf(float x) {
    return __fdividef(1.0f, 1.0f + __expf(-x));
}

// ---------------- graph preprocessing ----------------
__global__ void k_init_deg() {
    int i = blockIdx.x * blockDim.x + threadIdx.x;
    if (i < Nn) g_deg[i] = 1;  // self loop
}

__global__ void k_hist(const int* __restrict__ ei) {
    int e = blockIdx.x * blockDim.x + threadIdx.x;
    if (e < Ee) atomicAdd(&g_deg[ei[Ee + e]], 1);
}

__global__ void k_inv() {
    int i = blockIdx.x * blockDim.x + threadIdx.x;
    if (i < Nn) {
        g_inv[i] = rsqrtf((float)g_deg[i]);
        g_fill[i] = 0;
    }
}

__global__ void k_scan() {  // exclusive prefix over (deg-1), single block
    __shared__ int sh[1024];
    int tid = threadIdx.x;
    int loc[16];
    int s = 0;
#pragma unroll
    for (int i = 0; i < 16; i++) { loc[i] = g_deg[tid * 16 + i] - 1; s += loc[i]; }
    sh[tid] = s;
    __syncthreads();
    for (int off = 1; off < 1024; off <<= 1) {
        int v = (tid >= off) ? sh[tid - off] : 0;
        __syncthreads();
        sh[tid] += v;
        __syncthreads();
    }
    int ex = (tid == 0) ? 0 : sh[tid - 1];
#pragma unroll
    for (int i = 0; i < 16; i++) { g_ptr[tid * 16 + i] = ex; ex += loc[i]; }
    if (tid == 1023) g_ptr[Nn] = ex;
}

__global__ void k_scatter(const int* __restrict__ ei) {
    int e = blockIdx.x * blockDim.x + threadIdx.x;
    if (e >= Ee) return;
    int s = ei[e];
    int d = ei[Ee + e];
    int k = atomicAdd(&g_fill[d], 1);
    int idx = g_ptr[d] + k;
    g_src[idx] = s;
    g_w[idx] = g_inv[s] * g_inv[d];
}

// ---------------- GCN aggregate: out = relu?(sum_in + selfloop + bias) ----------------
__global__ void k_agg(const float* __restrict__ t, const float* __restrict__ bias,
                      float* __restrict__ out, int d, int relu) {
    int v = blockIdx.x;
    int f = threadIdx.x;
    float iv = g_inv[v];
    float acc = iv * iv * t[(size_t)v * d + f];
    int e0 = g_ptr[v], e1 = g_ptr[v + 1];
    for (int e = e0; e < e1; e++) {
        int s = g_src[e];
        float w = g_w[e];
        acc += w * t[(size_t)s * d + f];
    }
    acc += bias[f];
    if (relu) acc = fmaxf(acc, 0.0f);
    out[(size_t)v * d + f] = acc;
}

// ---------------- generic thin GEMM: C[M,Ncol] = A[M,K] @ W[K,Ncol] (+bias)(+relu) ----------------
// BM=128, BN=64, BK=16, 256 threads, 8x4 micro-tile in f32x2 (row pairs)
__global__ __launch_bounds__(256) void k_gemm(
    const float* __restrict__ A, const float* __restrict__ W,
    const float* __restrict__ bias, float* __restrict__ C,
    int K, int Ncol, int relu)
{
    __shared__ __align__(16) float As[128 * 17];
    __shared__ __align__(16) float Bs[16 * 64];
    int tid = threadIdx.x;
    int tx = tid & 15, ty = tid >> 4;
    int m0 = blockIdx.y * 128, n0 = blockIdx.x * 64;

    ull c2[4][4];
#pragma unroll
    for (int p = 0; p < 4; p++)
#pragma unroll
        for (int j = 0; j < 4; j++) c2[p][j] = 0ULL;

    for (int kb = 0; kb < K; kb += 16) {
#pragma unroll
        for (int q = 0; q < 8; q++) {
            int li = q * 256 + tid;
            int r = li >> 4, kk = li & 15, kg = kb + kk;
            As[r * 17 + kk] = (kg < K) ? A[(size_t)(m0 + r) * K + kg] : 0.0f;
        }
#pragma unroll
        for (int q = 0; q < 4; q++) {
            int li = q * 256 + tid;
            int kk = li >> 6, n = li & 63, kg = kb + kk;
            Bs[kk * 64 + n] = (kg < K && n0 + n < Ncol) ? W[(size_t)kg * Ncol + n0 + n] : 0.0f;
        }
        __syncthreads();
#pragma unroll
        for (int kk = 0; kk < 16; kk++) {
            float4 bv = *(const float4*)&Bs[kk * 64 + tx * 4];
            float a[8];
#pragma unroll
            for (int i = 0; i < 8; i++) a[i] = As[(ty * 8 + i) * 17 + kk];
            ull a2[4], bd[4];
            PK2(a2[0], a[0], a[1]); PK2(a2[1], a[2], a[3]);
            PK2(a2[2], a[4], a[5]); PK2(a2[3], a[6], a[7]);
            DUP2(bd[0], bv.x); DUP2(bd[1], bv.y); DUP2(bd[2], bv.z); DUP2(bd[3], bv.w);
#pragma unroll
            for (int p = 0; p < 4; p++)
#pragma unroll
                for (int j = 0; j < 4; j++) FMA2(c2[p][j], a2[p], bd[j]);
        }
        __syncthreads();
    }

#pragma unroll
    for (int p = 0; p < 4; p++) {
        int r0 = m0 + ty * 8 + 2 * p;
#pragma unroll
        for (int j = 0; j < 4; j++) {
            int col = n0 + tx * 4 + j;
            if (col < Ncol) {
                float lo, hi;
                UPK2(lo, hi, c2[p][j]);
                float bj = bias ? bias[col] : 0.0f;
                lo += bj; hi += bj;
                if (relu) { lo = fmaxf(lo, 0.0f); hi = fmaxf(hi, 0.0f); }
                C[(size_t)r0 * Ncol + col] = lo;
                C[(size_t)(r0 + 1) * Ncol + col] = hi;
            }
        }
    }
}

// ---------------- adjacency: C = sigmoid(L @ L^T), symmetric 128x128 tiles ----------------
// K=64 loaded whole. Panels stored k-major with 16B-granularity XOR swizzle.
__global__ __launch_bounds__(256) void k_adj(const float* __restrict__ L, float* __restrict__ C) {
    extern __shared__ float4 sm4[];
    int bx = blockIdx.x, by = blockIdx.y;
    if (bx < by) return;  // upper triangle of tile grid only
    float4* As4 = sm4;           // [64][32] f4, swizzled
    float4* Bs4 = sm4 + 2048;
    float* Asf = (float*)As4;
    float* Bsf = (float*)Bs4;
    int tid = threadIdx.x;
    int tx = tid & 15, ty = tid >> 4;
    int gi0 = by * 128, gj0 = bx * 128;
    const float4* L4 = (const float4*)L;

#pragma unroll
    for (int q = 0; q < 8; q++) {
        int fi = q * 256 + tid;
        int r = fi >> 4;       // 0..127
        int k4 = fi & 15;      // f4 index along K
        float4 va = L4[(size_t)(gi0 + r) * 16 + k4];
        float4 vb = L4[(size_t)(gj0 + r) * 16 + k4];
        const float* pa = (const float*)&va;
        const float* pb = (const float*)&vb;
#pragma unroll
        for (int c = 0; c < 4; c++) {
            int k = k4 * 4 + c;
            int p = (((r >> 2) ^ (k & 31)) << 2) | (r & 3);  // swizzled float index in row
            Asf[k * 128 + p] = pa[c];
            Bsf[k * 128 + p] = pb[c];
        }
    }
    __syncthreads();

    ull c2[4][8];
#pragma unroll
    for (int p = 0; p < 4; p++)
#pragma unroll
        for (int j = 0; j < 8; j++) c2[p][j] = 0ULL;

#pragma unroll 4
    for (int k = 0; k < 64; k++) {
        int sw = k & 31;
        float4 a0 = As4[k * 32 + ((ty * 2) ^ sw)];
        float4 a1 = As4[k * 32 + ((ty * 2 + 1) ^ sw)];
        float4 b0 = Bs4[k * 32 + ((tx * 2) ^ sw)];
        float4 b1 = Bs4[k * 32 + ((tx * 2 + 1) ^ sw)];
        ull ap[4], bd[8];
        PK2(ap[0], a0.x, a0.y); PK2(ap[1], a0.z, a0.w);
        PK2(ap[2], a1.x, a1.y); PK2(ap[3], a1.z, a1.w);
        DUP2(bd[0], b0.x); DUP2(bd[1], b0.y); DUP2(bd[2], b0.z); DUP2(bd[3], b0.w);
        DUP2(bd[4], b1.x); DUP2(bd[5], b1.y); DUP2(bd[6], b1.z); DUP2(bd[7], b1.w);
#pragma unroll
        for (int p = 0; p < 4; p++)
#pragma unroll
            for (int j = 0; j < 8; j++) FMA2(c2[p][j], ap[p], bd[j]);
    }

    // sigmoid in place
#pragma unroll
    for (int p = 0; p < 4; p++)
#pragma unroll
        for (int j = 0; j < 8; j++) {
            float lo, hi;
            UPK2(lo, hi, c2[p][j]);
            lo = sigf(lo);
            hi = sigf(hi);
            PK2(c2[p][j], lo, hi);
        }

    const size_t NN = (size_t)Nn;
    // normal orientation: coalesced float4 rows
#pragma unroll
    for (int p = 0; p < 4; p++) {
        float r0[8], r1[8];
#pragma unroll
        for (int j = 0; j < 8; j++) UPK2(r0[j], r1[j], c2[p][j]);
        size_t rowA = (size_t)(gi0 + ty * 8 + 2 * p) * NN + gj0 + tx * 8;
        size_t rowB = rowA + NN;
        *(float4*)&C[rowA]     = make_float4(r0[0], r0[1], r0[2], r0[3]);
        *(float4*)&C[rowA + 4] = make_float4(r0[4], r0[5], r0[6], r0[7]);
        *(float4*)&C[rowB]     = make_float4(r1[0], r1[1], r1[2], r1[3]);
        *(float4*)&C[rowB + 4] = make_float4(r1[4], r1[5], r1[6], r1[7]);
    }
    // mirrored tile (C is symmetric)
    if (bx != by) {
#pragma unroll
        for (int jj = 0; jj < 8; jj++) {
            float v[8];
#pragma unroll
            for (int p = 0; p < 4; p++) UPK2(v[2 * p], v[2 * p + 1], c2[p][jj]);
            size_t row = (size_t)(gj0 + tx * 8 + jj) * NN + gi0 + ty * 8;
            *(float4*)&C[row]     = make_float4(v[0], v[1], v[2], v[3]);
            *(float4*)&C[row + 4] = make_float4(v[4], v[5], v[6], v[7]);
        }
    }
}

// ---------------- per-graph max pool ----------------
__global__ void k_zgzero(float* zg) {
    int i = blockIdx.x * blockDim.x + threadIdx.x;
    if (i < Gg * 64) zg[i] = 0.0f;
}

__global__ void k_zgmax(const float* __restrict__ z, const int* __restrict__ batch,
                        float* __restrict__ zg) {
    int idx = blockIdx.x * blockDim.x + threadIdx.x;
    if (idx >= Nn * 64) return;
    int v = idx >> 6, f = idx & 63;
    // z >= 0 after relu, so int compare == float compare
    atomicMax((int*)&zg[batch[v] * 64 + f], __float_as_int(z[idx]));
}

// ---------------- launch ----------------
extern "C" void kernel_launch(void* const* d_in, const int* in_sizes, int n_in,
                              void* d_out, int out_size) {
    const float* x   = (const float*)d_in[0];
    const int*   ei  = (const int*)d_in[1];
    const int*   bat = (const int*)d_in[2];
    const float* Wg0 = (const float*)d_in[3];
    const float* bg0 = (const float*)d_in[4];
    const float* Wg1 = (const float*)d_in[5];
    const float* bg1 = (const float*)d_in[6];
    const float* Wg2 = (const float*)d_in[7];
    const float* bg2 = (const float*)d_in[8];
    const float* Wd0 = (const float*)d_in[9];
    const float* bd0 = (const float*)d_in[10];
    const float* Wd1 = (const float*)d_in[11];
    const float* bd1 = (const float*)d_in[12];
    const float* Wd2 = (const float*)d_in[13];
    const float* bd2 = (const float*)d_in[14];
    const float* We  = (const float*)d_in[15];
    const float* be  = (const float*)d_in[16];

    float* out = (float*)d_out;
    float* z   = out;                          // [N,64]
    float* zg  = out + (size_t)Nn * 64;        // [G,64]
    float* xr  = zg + (size_t)Gg * 64;         // [N,38]
    float* adj = xr + (size_t)Nn * 38;         // [N,N]

    float *t, *a;
    {
        void* p;
        cudaGetSymbolAddress(&p, g_t); t = (float*)p;
        cudaGetSymbolAddress(&p, g_a); a = (float*)p;
    }

    // GCN normalization + CSR build
    k_init_deg<<<64, 256>>>();
    k_hist<<<Ee / 256, 256>>>(ei);
    k_inv<<<64, 256>>>();
    k_scan<<<1, 1024>>>();
    k_scatter<<<Ee / 256, 256>>>(ei);

    auto ggrid = [](int ncol) { return dim3((unsigned)((ncol + 63) / 64), Nn / 128); };

    // encoder
    k_gemm<<<ggrid(256), 256>>>(x, Wg0, nullptr, t, 38, 256, 0);
    k_agg<<<Nn, 256>>>(t, bg0, a, 256, 1);
    k_gemm<<<ggrid(128), 256>>>(a, Wg1, nullptr, t, 256, 128, 0);
    k_agg<<<Nn, 128>>>(t, bg1, a, 128, 1);
    k_gemm<<<ggrid(64), 256>>>(a, Wg2, nullptr, t, 128, 64, 0);
    k_agg<<<Nn, 64>>>(t, bg2, z, 64, 1);

    // decoder
    k_gemm<<<ggrid(128), 256>>>(z, Wd0, bd0, a, 64, 128, 1);
    k_gemm<<<ggrid(256), 256>>>(a, Wd1, bd1, t, 128, 256, 1);
    k_gemm<<<ggrid(38), 256>>>(t, Wd2, bd2, xr, 256, 38, 0);

    // edge predictor logits -> g_a
    k_gemm<<<ggrid(64), 256>>>(z, We, be, a, 64, 64, 0);

    // per-graph max pool
    k_zgzero<<<(Gg * 64 + 255) / 256, 256>>>(zg);
    k_zgmax<<<(Nn * 64) / 256, 256>>>(z, bat, zg);

    // adjacency reconstruction
    cudaFuncSetAttribute(k_adj, cudaFuncAttributeMaxDynamicSharedMemorySize, 65536);
    k_adj<<<dim3(128, 128), 256, 65536>>>(a, adj);
}

// round 3
// speedup vs baseline: 1.1927x; 1.1927x over previous
#include <cuda_runtime.h>
#include <cuda_bf16.h>
#include <cstdint>

#define Nn 16384
#define Ee 262144
#define Gg 128

// ---------------- scratch (no allocations allowed) ----------------
__device__ float g_t[Nn * 256];     // transform output / bf16-split matrix (aliased)
__device__ float g_a[Nn * 256];     // activations / edge logits
__device__ int   g_deg[Nn];
__device__ float g_inv[Nn];
__device__ int   g_ptr[Nn + 1];
__device__ int   g_fill[Nn];
__device__ int   g_src[Ee];
__device__ float g_w[Ee];

typedef unsigned long long ull;

#define FMA2(c, a, b) asm("fma.rn.f32x2 %0, %1, %2, %0;" : "+l"(c) : "l"(a), "l"(b))
#define DUP2(o, x)    asm("mov.b64 %0, {%1, %1};" : "=l"(o) : "f"(x))
#define PK2(o, x, y)  asm("mov.b64 %0, {%1, %2};" : "=l"(o) : "f"(x), "f"(y))
#define UPK2(x, y, c) asm("mov.b64 {%0, %1}, %2;" : "=f"(x), "=f"(y) : "l"(c))

__device__ __forceinline__ float sigf(float x) {
    return __fdividef(1.0f, 1.0f + __expf(-x));
}

__device__ __forceinline__ uint32_t smem_u32(const void* p) {
    uint32_t a;
    asm("{ .reg .u64 t; cvta.to.shared.u64 t, %1; cvt.u32.u64 %0, t; }" : "=r"(a) : "l"(p));
    return a;
}

__device__ __forceinline__ void ldsm_x4(uint32_t addr, uint32_t* r) {
    asm volatile("ldmatrix.sync.aligned.m8n8.x4.shared.b16 {%0,%1,%2,%3}, [%4];"
        : "=r"(r[0]), "=r"(r[1]), "=r"(r[2]), "=r"(r[3]) : "r"(addr));
}

__device__ __forceinline__ void mma_bf16(float* c, const uint32_t* a, const uint32_t* b) {
    asm volatile("mma.sync.aligned.m16n8k16.row.col.f32.bf16.bf16.f32 "
        "{%0,%1,%2,%3}, {%4,%5,%6,%7}, {%8,%9}, {%0,%1,%2,%3};"
        : "+f"(c[0]), "+f"(c[1]), "+f"(c[2]), "+f"(c[3])
        : "r"(a[0]), "r"(a[1]), "r"(a[2]), "r"(a[3]), "r"(b[0]), "r"(b[1]));
}

// ---------------- graph preprocessing ----------------
__global__ void k_init_deg() {
    int i = blockIdx.x * blockDim.x + threadIdx.x;
    if (i < Nn) g_deg[i] = 1;  // self loop
}

__global__ void k_hist(const int* __restrict__ ei) {
    int e = blockIdx.x * blockDim.x + threadIdx.x;
    if (e < Ee) atomicAdd(&g_deg[ei[Ee + e]], 1);
}

__global__ void k_inv() {
    int i = blockIdx.x * blockDim.x + threadIdx.x;
    if (i < Nn) {
        g_inv[i] = rsqrtf((float)g_deg[i]);
        g_fill[i] = 0;
    }
}

__global__ void k_scan() {  // exclusive prefix over (deg-1), single block
    __shared__ int sh[1024];
    int tid = threadIdx.x;
    int loc[16];
    int s = 0;
#pragma unroll
    for (int i = 0; i < 16; i++) { loc[i] = g_deg[tid * 16 + i] - 1; s += loc[i]; }
    sh[tid] = s;
    __syncthreads();
    for (int off = 1; off < 1024; off <<= 1) {
        int v = (tid >= off) ? sh[tid - off] : 0;
        __syncthreads();
        sh[tid] += v;
        __syncthreads();
    }
    int ex = (tid == 0) ? 0 : sh[tid - 1];
#pragma unroll
    for (int i = 0; i < 16; i++) { g_ptr[tid * 16 + i] = ex; ex += loc[i]; }
    if (tid == 1023) g_ptr[Nn] = ex;
}

__global__ void k_scatter(const int* __restrict__ ei) {
    int e = blockIdx.x * blockDim.x + threadIdx.x;
    if (e >= Ee) return;
    int s = ei[e];
    int d = ei[Ee + e];
    int k = atomicAdd(&g_fill[d], 1);
    int idx = g_ptr[d] + k;
    g_src[idx] = s;
    g_w[idx] = g_inv[s] * g_inv[d];
}

// ---------------- GCN aggregate ----------------
__global__ void k_agg(const float* __restrict__ t, const float* __restrict__ bias,
                      float* __restrict__ out, int d, int relu) {
    int v = blockIdx.x;
    int f = threadIdx.x;
    float iv = g_inv[v];
    float acc = iv * iv * t[(size_t)v * d + f];
    int e0 = g_ptr[v], e1 = g_ptr[v + 1];
    int e = e0;
    for (; e + 4 <= e1; e += 4) {
        int s0 = g_src[e], s1 = g_src[e + 1], s2 = g_src[e + 2], s3 = g_src[e + 3];
        float w0 = g_w[e], w1 = g_w[e + 1], w2 = g_w[e + 2], w3 = g_w[e + 3];
        float t0 = t[(size_t)s0 * d + f];
        float t1 = t[(size_t)s1 * d + f];
        float t2 = t[(size_t)s2 * d + f];
        float t3 = t[(size_t)s3 * d + f];
        acc += w0 * t0; acc += w1 * t1; acc += w2 * t2; acc += w3 * t3;
    }
    for (; e < e1; e++) acc += g_w[e] * t[(size_t)g_src[e] * d + f];
    acc += bias[f];
    if (relu) acc = fmaxf(acc, 0.0f);
    out[(size_t)v * d + f] = acc;
}

// ---------------- generic thin GEMM ----------------
__global__ __launch_bounds__(256) void k_gemm(
    const float* __restrict__ A, const float* __restrict__ W,
    const float* __restrict__ bias, float* __restrict__ C,
    int K, int Ncol, int relu)
{
    __shared__ __align__(16) float As[128 * 17];
    __shared__ __align__(16) float Bs[16 * 64];
    int tid = threadIdx.x;
    int tx = tid & 15, ty = tid >> 4;
    int m0 = blockIdx.y * 128, n0 = blockIdx.x * 64;

    ull c2[4][4];
#pragma unroll
    for (int p = 0; p < 4; p++)
#pragma unroll
        for (int j = 0; j < 4; j++) c2[p][j] = 0ULL;

    for (int kb = 0; kb < K; kb += 16) {
#pragma unroll
        for (int q = 0; q < 8; q++) {
            int li = q * 256 + tid;
            int r = li >> 4, kk = li & 15, kg = kb + kk;
            As[r * 17 + kk] = (kg < K) ? A[(size_t)(m0 + r) * K + kg] : 0.0f;
        }
#pragma unroll
        for (int q = 0; q < 4; q++) {
            int li = q * 256 + tid;
            int kk = li >> 6, n = li & 63, kg = kb + kk;
            Bs[kk * 64 + n] = (kg < K && n0 + n < Ncol) ? W[(size_t)kg * Ncol + n0 + n] : 0.0f;
        }
        __syncthreads();
#pragma unroll
        for (int kk = 0; kk < 16; kk++) {
            float4 bv = *(const float4*)&Bs[kk * 64 + tx * 4];
            float a[8];
#pragma unroll
            for (int i = 0; i < 8; i++) a[i] = As[(ty * 8 + i) * 17 + kk];
            ull a2[4], bd[4];
            PK2(a2[0], a[0], a[1]); PK2(a2[1], a[2], a[3]);
            PK2(a2[2], a[4], a[5]); PK2(a2[3], a[6], a[7]);
            DUP2(bd[0], bv.x); DUP2(bd[1], bv.y); DUP2(bd[2], bv.z); DUP2(bd[3], bv.w);
#pragma unroll
            for (int p = 0; p < 4; p++)
#pragma unroll
                for (int j = 0; j < 4; j++) FMA2(c2[p][j], a2[p], bd[j]);
        }
        __syncthreads();
    }

#pragma unroll
    for (int p = 0; p < 4; p++) {
        int r0 = m0 + ty * 8 + 2 * p;
#pragma unroll
        for (int j = 0; j < 4; j++) {
            int col = n0 + tx * 4 + j;
            if (col < Ncol) {
                float lo, hi;
                UPK2(lo, hi, c2[p][j]);
                float bj = bias ? bias[col] : 0.0f;
                lo += bj; hi += bj;
                if (relu) { lo = fmaxf(lo, 0.0f); hi = fmaxf(hi, 0.0f); }
                C[(size_t)r0 * Ncol + col] = lo;
                C[(size_t)(r0 + 1) * Ncol + col] = hi;
            }
        }
    }
}

// ---------------- bf16 split: logits[N,64] -> Lb[N,128] = [hi | lo] ----------------
__global__ void k_split(const float* __restrict__ a, __nv_bfloat16* __restrict__ Lb) {
    int i = blockIdx.x * blockDim.x + threadIdx.x;
    if (i >= Nn * 64) return;
    int v = i >> 6, k = i & 63;
    float x = a[i];
    __nv_bfloat16 hi = __float2bfloat16(x);
    float lo = x - __bfloat162float(hi);
    Lb[(size_t)v * 128 + k] = hi;
    Lb[(size_t)v * 128 + 64 + k] = __float2bfloat16(lo);
}

// ---------------- adjacency via mma.sync bf16: C = sigmoid(Lb @ Lb^T) ----------------
// 128x128 tile per CTA, 256 thr (8 warps, 2x4), warp tile m64n32, K=128.
// Panels in smem (bf16, XOR-swizzled uint4), epilogue staged through smem tile
// (reuses panel space) for coalesced normal + mirrored writes.
#define ADJ_SMEM 65536

__global__ __launch_bounds__(256) void k_adj_mma(const __nv_bfloat16* __restrict__ Lb,
                                                 float* __restrict__ C) {
    int bx = blockIdx.x, by = blockIdx.y;
    if (bx < by) return;
    extern __shared__ __align__(16) char smem[];
    char* smA = smem;            // 128 rows x 256B
    char* smB = smem + 32768;
    int tid = threadIdx.x;
    int w = tid >> 5, l = tid & 31;
    int wm = w & 1, wn = w >> 1;        // warp grid 2 (M) x 4 (N)
    int gi0 = by * 128, gj0 = bx * 128;
    bool diag = (bx == by);

    // ---- panel loads: warp covers 2 rows x 16 uint4 (coalesced), swizzled store
    {
        const uint4* A4 = (const uint4*)(Lb + (size_t)gi0 * 128);
        const uint4* B4 = (const uint4*)(Lb + (size_t)gj0 * 128);
        int c = tid & 15;
#pragma unroll
        for (int it = 0; it < 8; it++) {
            int r = (tid >> 4) + it * 16;
            int swz = c ^ (r & 7);
            *(uint4*)(smA + r * 256 + swz * 16) = A4[r * 16 + c];
            if (!diag) *(uint4*)(smB + r * 256 + swz * 16) = B4[r * 16 + c];
        }
    }
    __syncthreads();

    uint32_t aA = smem_u32(smA);
    uint32_t aB = diag ? aA : smem_u32(smB);

    float acc[4][4][4];
#pragma unroll
    for (int mi = 0; mi < 4; mi++)
#pragma unroll
        for (int nj = 0; nj < 4; nj++)
#pragma unroll
            for (int q = 0; q < 4; q++) acc[mi][nj][q] = 0.0f;

#pragma unroll
    for (int s = 0; s < 8; s++) {
        uint32_t af[4][4], bf[2][4];
#pragma unroll
        for (int mi = 0; mi < 4; mi++) {
            int row = wm * 64 + mi * 16 + (l & 15);
            int c = (s * 2 + (l >> 4)) ^ (row & 7);
            ldsm_x4(aA + row * 256 + c * 16, af[mi]);
        }
#pragma unroll
        for (int njp = 0; njp < 2; njp++) {
            int n = wn * 32 + njp * 16 + (l & 7) + ((l >> 4) << 3);
            int c = (s * 2 + ((l >> 3) & 1)) ^ (n & 7);
            ldsm_x4(aB + n * 256 + c * 16, bf[njp]);
        }
#pragma unroll
        for (int mi = 0; mi < 4; mi++)
#pragma unroll
            for (int nj = 0; nj < 4; nj++)
                mma_bf16(acc[mi][nj], af[mi], &bf[nj >> 1][(nj & 1) * 2]);
    }

    __syncthreads();  // panels dead; reuse smem as fp32 tile [128][128], f4-swizzled

    float* tile = (float*)smem;
    // stage fragments (sigmoid applied)
#pragma unroll
    for (int mi = 0; mi < 4; mi++) {
        int r0 = wm * 64 + mi * 16 + (l >> 2);
#pragma unroll
        for (int nj = 0; nj < 4; nj++) {
            int col = wn * 32 + nj * 8 + 2 * (l & 3);
#pragma unroll
            for (int h = 0; h < 2; h++) {  // h=0: rows r0, h=1: r0+8
                int r = r0 + h * 8;
                int idx4 = r * 32 + ((col >> 2) ^ (r & 31));
                float v0 = sigf(acc[mi][nj][2 * h]);
                float v1 = sigf(acc[mi][nj][2 * h + 1]);
                tile[idx4 * 4 + (col & 3)] = v0;
                tile[idx4 * 4 + (col & 3) + 1] = v1;
            }
        }
    }
    __syncthreads();

    const size_t NN = (size_t)Nn;
    // normal orientation: float4 coalesced rows
#pragma unroll
    for (int it = 0; it < 16; it++) {
        int idx = it * 256 + tid;
        int r = idx >> 5, c4 = idx & 31;
        float4 v = *(float4*)&tile[(r * 32 + (c4 ^ (r & 31))) * 4];
        *(float4*)&C[(size_t)(gi0 + r) * NN + gj0 + c4 * 4] = v;
    }
    // mirrored tile (symmetry): transpose read from smem, coalesced float4 rows
    if (!diag) {
#pragma unroll
        for (int it = 0; it < 16; it++) {
            int idx = it * 256 + tid;
            int colT = idx >> 5, rT = idx & 31;   // warp: fixed colT, rT 0..31
            float v[4];
#pragma unroll
            for (int i = 0; i < 4; i++) {
                int r = rT * 4 + i;
                v[i] = tile[(r * 32 + ((colT >> 2) ^ (r & 31))) * 4 + (colT & 3)];
            }
            *(float4*)&C[(size_t)(gj0 + colT) * NN + gi0 + rT * 4] =
                make_float4(v[0], v[1], v[2], v[3]);
        }
    }
}

// ---------------- per-graph max pool ----------------
__global__ void k_zgzero(float* zg) {
    int i = blockIdx.x * blockDim.x + threadIdx.x;
    if (i < Gg * 64) zg[i] = 0.0f;
}

__global__ void k_zgmax(const float* __restrict__ z, const int* __restrict__ batch,
                        float* __restrict__ zg) {
    int idx = blockIdx.x * blockDim.x + threadIdx.x;
    if (idx >= Nn * 64) return;
    int v = idx >> 6, f = idx & 63;
    atomicMax((int*)&zg[batch[v] * 64 + f], __float_as_int(z[idx]));
}

// ---------------- launch ----------------
extern "C" void kernel_launch(void* const* d_in, const int* in_sizes, int n_in,
                              void* d_out, int out_size) {
    const float* x   = (const float*)d_in[0];
    const int*   ei  = (const int*)d_in[1];
    const int*   bat = (const int*)d_in[2];
    const float* Wg0 = (const float*)d_in[3];
    const float* bg0 = (const float*)d_in[4];
    const float* Wg1 = (const float*)d_in[5];
    const float* bg1 = (const float*)d_in[6];
    const float* Wg2 = (const float*)d_in[7];
    const float* bg2 = (const float*)d_in[8];
    const float* Wd0 = (const float*)d_in[9];
    const float* bd0 = (const float*)d_in[10];
    const float* Wd1 = (const float*)d_in[11];
    const float* bd1 = (const float*)d_in[12];
    const float* Wd2 = (const float*)d_in[13];
    const float* bd2 = (const float*)d_in[14];
    const float* We  = (const float*)d_in[15];
    const float* be  = (const float*)d_in[16];

    float* out = (float*)d_out;
    float* z   = out;                          // [N,64]
    float* zg  = out + (size_t)Nn * 64;        // [G,64]
    float* xr  = zg + (size_t)Gg * 64;         // [N,38]
    float* adj = xr + (size_t)Nn * 38;         // [N,N]

    float *t, *a;
    {
        void* p;
        cudaGetSymbolAddress(&p, g_t); t = (float*)p;
        cudaGetSymbolAddress(&p, g_a); a = (float*)p;
    }
    __nv_bfloat16* Lb = (__nv_bfloat16*)t;     // alias (t dead by split time)

    // GCN normalization + CSR build
    k_init_deg<<<64, 256>>>();
    k_hist<<<Ee / 256, 256>>>(ei);
    k_inv<<<64, 256>>>();
    k_scan<<<1, 1024>>>();
    k_scatter<<<Ee / 256, 256>>>(ei);

    auto ggrid = [](int ncol) { return dim3((unsigned)((ncol + 63) / 64), Nn / 128); };

    // encoder
    k_gemm<<<ggrid(256), 256>>>(x, Wg0, nullptr, t, 38, 256, 0);
    k_agg<<<Nn, 256>>>(t, bg0, a, 256, 1);
    k_gemm<<<ggrid(128), 256>>>(a, Wg1, nullptr, t, 256, 128, 0);
    k_agg<<<Nn, 128>>>(t, bg1, a, 128, 1);
    k_gemm<<<ggrid(64), 256>>>(a, Wg2, nullptr, t, 128, 64, 0);
    k_agg<<<Nn, 64>>>(t, bg2, z, 64, 1);

    // decoder
    k_gemm<<<ggrid(128), 256>>>(z, Wd0, bd0, a, 64, 128, 1);
    k_gemm<<<ggrid(256), 256>>>(a, Wd1, bd1, t, 128, 256, 1);
    k_gemm<<<ggrid(38), 256>>>(t, Wd2, bd2, xr, 256, 38, 0);

    // edge predictor logits -> a
    k_gemm<<<ggrid(64), 256>>>(z, We, be, a, 64, 64, 0);

    // per-graph max pool
    k_zgzero<<<(Gg * 64 + 255) / 256, 256>>>(zg);
    k_zgmax<<<(Nn * 64) / 256, 256>>>(z, bat, zg);

    // bf16 split + tensor-core adjacency
    k_split<<<(Nn * 64) / 256, 256>>>(a, Lb);
    cudaFuncSetAttribute(k_adj_mma, cudaFuncAttributeMaxDynamicSharedMemorySize, ADJ_SMEM);
    k_adj_mma<<<dim3(128, 128), 256, ADJ_SMEM>>>(Lb, adj);
}

// round 4
// speedup vs baseline: 1.2816x; 1.0745x over previous
#include <cuda_runtime.h>
#include <cuda_bf16.h>
#include <cstdint>

#define Nn 16384
#define Ee 262144
#define Gg 128

// ---------------- scratch (no allocations allowed) ----------------
__device__ float g_t[Nn * 256];     // transform output / bf16-split matrix (aliased)
__device__ float g_a[Nn * 256];     // activations
__device__ int   g_deg[Nn];
__device__ float g_inv[Nn];
__device__ int   g_ptr[Nn + 1];
__device__ int   g_fill[Nn];
__device__ int   g_src[Ee];
__device__ float g_w[Ee];

typedef unsigned long long ull;

#define FMA2(c, a, b) asm("fma.rn.f32x2 %0, %1, %2, %0;" : "+l"(c) : "l"(a), "l"(b))
#define DUP2(o, x)    asm("mov.b64 %0, {%1, %1};" : "=l"(o) : "f"(x))
#define PK2(o, x, y)  asm("mov.b64 %0, {%1, %2};" : "=l"(o) : "f"(x), "f"(y))
#define UPK2(x, y, c) asm("mov.b64 {%0, %1}, %2;" : "=f"(x), "=f"(y) : "l"(c))

__device__ __forceinline__ float sigf(float x) {
    return __fdividef(1.0f, 1.0f + __expf(-x));
}

__device__ __forceinline__ uint32_t smem_u32(const void* p) {
    uint32_t a;
    asm("{ .reg .u64 t; cvta.to.shared.u64 t, %1; cvt.u32.u64 %0, t; }" : "=r"(a) : "l"(p));
    return a;
}

__device__ __forceinline__ void ldsm_x4(uint32_t addr, uint32_t* r) {
    asm volatile("ldmatrix.sync.aligned.m8n8.x4.shared.b16 {%0,%1,%2,%3}, [%4];"
        : "=r"(r[0]), "=r"(r[1]), "=r"(r[2]), "=r"(r[3]) : "r"(addr));
}

__device__ __forceinline__ void mma_bf16(float* c, const uint32_t* a, const uint32_t* b) {
    asm volatile("mma.sync.aligned.m16n8k16.row.col.f32.bf16.bf16.f32 "
        "{%0,%1,%2,%3}, {%4,%5,%6,%7}, {%8,%9}, {%0,%1,%2,%3};"
        : "+f"(c[0]), "+f"(c[1]), "+f"(c[2]), "+f"(c[3])
        : "r"(a[0]), "r"(a[1]), "r"(a[2]), "r"(a[3]), "r"(b[0]), "r"(b[1]));
}

// ---------------- graph preprocessing ----------------
__global__ void k_init_deg() {
    int i = blockIdx.x * blockDim.x + threadIdx.x;
    if (i < Nn) g_deg[i] = 1;  // self loop
}

__global__ void k_hist(const int* __restrict__ ei) {
    int e = blockIdx.x * blockDim.x + threadIdx.x;
    if (e < Ee) atomicAdd(&g_deg[ei[Ee + e]], 1);
}

__global__ void k_inv(float* __restrict__ zg) {
    int i = blockIdx.x * blockDim.x + threadIdx.x;
    if (i < Nn) {
        g_inv[i] = rsqrtf((float)g_deg[i]);
        g_fill[i] = 0;
    }
    if (i < Gg * 64) zg[i] = 0.0f;   // zero pooled output (fused)
}

__global__ void k_scan() {  // exclusive prefix over (deg-1), warp-shfl based
    __shared__ int wsum[32];
    int tid = threadIdx.x, lane = tid & 31, wid = tid >> 5;
    int loc[16];
    int s = 0;
#pragma unroll
    for (int i = 0; i < 16; i++) { loc[i] = g_deg[tid * 16 + i] - 1; s += loc[i]; }
    int inc = s;
#pragma unroll
    for (int off = 1; off < 32; off <<= 1) {
        int v = __shfl_up_sync(0xFFFFFFFF, inc, off);
        if (lane >= off) inc += v;
    }
    if (lane == 31) wsum[wid] = inc;
    __syncthreads();
    if (wid == 0) {
        int v = wsum[lane];
#pragma unroll
        for (int off = 1; off < 32; off <<= 1) {
            int u = __shfl_up_sync(0xFFFFFFFF, v, off);
            if (lane >= off) v += u;
        }
        wsum[lane] = v;
    }
    __syncthreads();
    int ex = (wid ? wsum[wid - 1] : 0) + inc - s;  // exclusive base for this thread
#pragma unroll
    for (int i = 0; i < 16; i++) { g_ptr[tid * 16 + i] = ex; ex += loc[i]; }
    if (tid == 1023) g_ptr[Nn] = ex;
}

__global__ void k_scatter(const int* __restrict__ ei) {
    int e = blockIdx.x * blockDim.x + threadIdx.x;
    if (e >= Ee) return;
    int s = ei[e];
    int d = ei[Ee + e];
    int k = atomicAdd(&g_fill[d], 1);
    int idx = g_ptr[d] + k;
    g_src[idx] = s;
    g_w[idx] = g_inv[s] * g_inv[d];
}

// ---------------- GCN aggregate (optionally fused zg max pool) ----------------
__global__ void k_agg(const float* __restrict__ t, const float* __restrict__ bias,
                      float* __restrict__ out, int d, int relu,
                      const int* __restrict__ batch, float* __restrict__ zg) {
    int v = blockIdx.x;
    int f = threadIdx.x;
    float iv = g_inv[v];
    float acc = iv * iv * t[(size_t)v * d + f];
    int e0 = g_ptr[v], e1 = g_ptr[v + 1];
    int e = e0;
    for (; e + 8 <= e1; e += 8) {
        float p = 0.0f, q = 0.0f;
#pragma unroll
        for (int u = 0; u < 8; u += 2) {
            int s0 = g_src[e + u], s1 = g_src[e + u + 1];
            float w0 = g_w[e + u], w1 = g_w[e + u + 1];
            p += w0 * t[(size_t)s0 * d + f];
            q += w1 * t[(size_t)s1 * d + f];
        }
        acc += p + q;
    }
    for (; e + 4 <= e1; e += 4) {
        int s0 = g_src[e], s1 = g_src[e + 1], s2 = g_src[e + 2], s3 = g_src[e + 3];
        float w0 = g_w[e], w1 = g_w[e + 1], w2 = g_w[e + 2], w3 = g_w[e + 3];
        acc += w0 * t[(size_t)s0 * d + f];
        acc += w1 * t[(size_t)s1 * d + f];
        acc += w2 * t[(size_t)s2 * d + f];
        acc += w3 * t[(size_t)s3 * d + f];
    }
    for (; e < e1; e++) acc += g_w[e] * t[(size_t)g_src[e] * d + f];
    acc += bias[f];
    if (relu) acc = fmaxf(acc, 0.0f);
    out[(size_t)v * d + f] = acc;
    if (zg) atomicMax((int*)&zg[batch[v] * 64 + f], __float_as_int(acc));
}

// ---------------- generic thin GEMM (k-major A panel, vector broadcast loads) ----------------
// BM=128, BN=64, BK=16, 256 threads, 8x4 micro-tile in f32x2.
// Optional fused bf16-split epilogue (Ncol must be 64): writes [hi|lo] rows of 128.
__global__ __launch_bounds__(256) void k_gemm(
    const float* __restrict__ A, const float* __restrict__ W,
    const float* __restrict__ bias, float* __restrict__ C,
    int K, int Ncol, int relu, __nv_bfloat16* __restrict__ splitOut)
{
    __shared__ __align__(16) float As[16 * 132];   // [k][m], stride 132
    __shared__ __align__(16) float Bs[16 * 64];
    int tid = threadIdx.x;
    int tx = tid & 15, ty = tid >> 4;
    int m0 = blockIdx.y * 128, n0 = blockIdx.x * 64;

    ull c2[4][4];
#pragma unroll
    for (int p = 0; p < 4; p++)
#pragma unroll
        for (int j = 0; j < 4; j++) c2[p][j] = 0ULL;

    for (int kb = 0; kb < K; kb += 16) {
#pragma unroll
        for (int q = 0; q < 8; q++) {
            int li = q * 256 + tid;
            int r = li >> 4, kk = li & 15, kg = kb + kk;
            As[kk * 132 + r] = (kg < K) ? A[(size_t)(m0 + r) * K + kg] : 0.0f;
        }
#pragma unroll
        for (int q = 0; q < 4; q++) {
            int li = q * 256 + tid;
            int kk = li >> 6, n = li & 63, kg = kb + kk;
            Bs[kk * 64 + n] = (kg < K && n0 + n < Ncol) ? W[(size_t)kg * Ncol + n0 + n] : 0.0f;
        }
        __syncthreads();
#pragma unroll
        for (int kk = 0; kk < 16; kk++) {
            float4 bv = *(const float4*)&Bs[kk * 64 + tx * 4];
            float4 a0 = *(const float4*)&As[kk * 132 + ty * 8];
            float4 a1 = *(const float4*)&As[kk * 132 + ty * 8 + 4];
            ull a2[4], bd[4];
            PK2(a2[0], a0.x, a0.y); PK2(a2[1], a0.z, a0.w);
            PK2(a2[2], a1.x, a1.y); PK2(a2[3], a1.z, a1.w);
            DUP2(bd[0], bv.x); DUP2(bd[1], bv.y); DUP2(bd[2], bv.z); DUP2(bd[3], bv.w);
#pragma unroll
            for (int p = 0; p < 4; p++)
#pragma unroll
                for (int j = 0; j < 4; j++) FMA2(c2[p][j], a2[p], bd[j]);
        }
        __syncthreads();
    }

#pragma unroll
    for (int p = 0; p < 4; p++) {
        int r0 = m0 + ty * 8 + 2 * p;
#pragma unroll
        for (int j = 0; j < 4; j++) {
            int col = n0 + tx * 4 + j;
            if (col < Ncol) {
                float lo, hi;
                UPK2(lo, hi, c2[p][j]);
                float bj = bias ? bias[col] : 0.0f;
                lo += bj; hi += bj;
                if (relu) { lo = fmaxf(lo, 0.0f); hi = fmaxf(hi, 0.0f); }
                if (splitOut) {   // Ncol==64: write bf16 split rows [hi64|lo64]
                    __nv_bfloat16 h0 = __float2bfloat16(lo);
                    __nv_bfloat16 h1 = __float2bfloat16(hi);
                    splitOut[(size_t)r0 * 128 + col] = h0;
                    splitOut[(size_t)r0 * 128 + 64 + col] = __float2bfloat16(lo - __bfloat162float(h0));
                    splitOut[(size_t)(r0 + 1) * 128 + col] = h1;
                    splitOut[(size_t)(r0 + 1) * 128 + 64 + col] = __float2bfloat16(hi - __bfloat162float(h1));
                } else {
                    C[(size_t)r0 * Ncol + col] = lo;
                    C[(size_t)(r0 + 1) * Ncol + col] = hi;
                }
            }
        }
    }
}

// ---------------- adjacency via mma.sync bf16: C = sigmoid(Lb @ Lb^T) ----------------
// 1D triangular grid (8256 CTAs). 128x128 tile, 8 warps (2x4), warp tile m64n32, K=128.
#define ADJ_SMEM 65536

__global__ __launch_bounds__(256) void k_adj_mma(const __nv_bfloat16* __restrict__ Lb,
                                                 float* __restrict__ C) {
    // linear -> lower-triangle (p >= q): bx = p, by = q
    int ti = blockIdx.x;
    int p = (int)((sqrtf(8.0f * ti + 1.0f) - 1.0f) * 0.5f);
    while ((p + 1) * (p + 2) / 2 <= ti) p++;
    while (p * (p + 1) / 2 > ti) p--;
    int bx = p, by = ti - p * (p + 1) / 2;

    extern __shared__ __align__(16) char smem[];
    char* smA = smem;            // 128 rows x 256B
    char* smB = smem + 32768;
    int tid = threadIdx.x;
    int w = tid >> 5, l = tid & 31;
    int wm = w & 1, wn = w >> 1;        // warp grid 2 (M) x 4 (N)
    int gi0 = by * 128, gj0 = bx * 128;
    bool diag = (bx == by);

    // ---- panel loads: coalesced uint4, XOR-swizzled store
    {
        const uint4* A4 = (const uint4*)(Lb + (size_t)gi0 * 128);
        const uint4* B4 = (const uint4*)(Lb + (size_t)gj0 * 128);
        int c = tid & 15;
#pragma unroll
        for (int it = 0; it < 8; it++) {
            int r = (tid >> 4) + it * 16;
            int swz = c ^ (r & 7);
            *(uint4*)(smA + r * 256 + swz * 16) = A4[r * 16 + c];
            if (!diag) *(uint4*)(smB + r * 256 + swz * 16) = B4[r * 16 + c];
        }
    }
    __syncthreads();

    uint32_t aA = smem_u32(smA);
    uint32_t aB = diag ? aA : smem_u32(smB);

    float acc[4][4][4];
#pragma unroll
    for (int mi = 0; mi < 4; mi++)
#pragma unroll
        for (int nj = 0; nj < 4; nj++)
#pragma unroll
            for (int q = 0; q < 4; q++) acc[mi][nj][q] = 0.0f;

#pragma unroll
    for (int s = 0; s < 8; s++) {
        uint32_t af[4][4], bf[2][4];
#pragma unroll
        for (int mi = 0; mi < 4; mi++) {
            int row = wm * 64 + mi * 16 + (l & 15);
            int c = (s * 2 + (l >> 4)) ^ (row & 7);
            ldsm_x4(aA + row * 256 + c * 16, af[mi]);
        }
#pragma unroll
        for (int njp = 0; njp < 2; njp++) {
            int n = wn * 32 + njp * 16 + (l & 7) + ((l >> 4) << 3);
            int c = (s * 2 + ((l >> 3) & 1)) ^ (n & 7);
            ldsm_x4(aB + n * 256 + c * 16, bf[njp]);
        }
#pragma unroll
        for (int mi = 0; mi < 4; mi++)
#pragma unroll
            for (int nj = 0; nj < 4; nj++)
                mma_bf16(acc[mi][nj], af[mi], &bf[nj >> 1][(nj & 1) * 2]);
    }

    __syncthreads();  // panels dead; reuse smem as fp32 tile [128][128], f4-swizzled

    float* tile = (float*)smem;
#pragma unroll
    for (int mi = 0; mi < 4; mi++) {
        int r0 = wm * 64 + mi * 16 + (l >> 2);
#pragma unroll
        for (int nj = 0; nj < 4; nj++) {
            int col = wn * 32 + nj * 8 + 2 * (l & 3);
#pragma unroll
            for (int h = 0; h < 2; h++) {
                int r = r0 + h * 8;
                int idx4 = r * 32 + ((col >> 2) ^ (r & 31));
                tile[idx4 * 4 + (col & 3)] = sigf(acc[mi][nj][2 * h]);
                tile[idx4 * 4 + (col & 3) + 1] = sigf(acc[mi][nj][2 * h + 1]);
            }
        }
    }
    __syncthreads();

    const size_t NN = (size_t)Nn;
#pragma unroll
    for (int it = 0; it < 16; it++) {
        int idx = it * 256 + tid;
        int r = idx >> 5, c4 = idx & 31;
        float4 v = *(float4*)&tile[(r * 32 + (c4 ^ (r & 31))) * 4];
        *(float4*)&C[(size_t)(gi0 + r) * NN + gj0 + c4 * 4] = v;
    }
    if (!diag) {
#pragma unroll
        for (int it = 0; it < 16; it++) {
            int idx = it * 256 + tid;
            int colT = idx >> 5, rT = idx & 31;
            float v[4];
#pragma unroll
            for (int i = 0; i < 4; i++) {
                int r = rT * 4 + i;
                v[i] = tile[(r * 32 + ((colT >> 2) ^ (r & 31))) * 4 + (colT & 3)];
            }
            *(float4*)&C[(size_t)(gj0 + colT) * NN + gi0 + rT * 4] =
                make_float4(v[0], v[1], v[2], v[3]);
        }
    }
}

// ---------------- launch ----------------
extern "C" void kernel_launch(void* const* d_in, const int* in_sizes, int n_in,
                              void* d_out, int out_size) {
    const float* x   = (const float*)d_in[0];
    const int*   ei  = (const int*)d_in[1];
    const int*   bat = (const int*)d_in[2];
    const float* Wg0 = (const float*)d_in[3];
    const float* bg0 = (const float*)d_in[4];
    const float* Wg1 = (const float*)d_in[5];
    const float* bg1 = (const float*)d_in[6];
    const float* Wg2 = (const float*)d_in[7];
    const float* bg2 = (const float*)d_in[8];
    const float* Wd0 = (const float*)d_in[9];
    const float* bd0 = (const float*)d_in[10];
    const float* Wd1 = (const float*)d_in[11];
    const float* bd1 = (const float*)d_in[12];
    const float* Wd2 = (const float*)d_in[13];
    const float* bd2 = (const float*)d_in[14];
    const float* We  = (const float*)d_in[15];
    const float* be  = (const float*)d_in[16];

    float* out = (float*)d_out;
    float* z   = out;                          // [N,64]
    float* zg  = out + (size_t)Nn * 64;        // [G,64]
    float* xr  = zg + (size_t)Gg * 64;         // [N,38]
    float* adj = xr + (size_t)Nn * 38;         // [N,N]

    float *t, *a;
    {
        void* p;
        cudaGetSymbolAddress(&p, g_t); t = (float*)p;
        cudaGetSymbolAddress(&p, g_a); a = (float*)p;
    }
    __nv_bfloat16* Lb = (__nv_bfloat16*)t;     // alias (t dead by split time)

    // GCN normalization + CSR build
    k_init_deg<<<64, 256>>>();
    k_hist<<<Ee / 256, 256>>>(ei);
    k_inv<<<64, 256>>>(zg);
    k_scan<<<1, 1024>>>();
    k_scatter<<<Ee / 256, 256>>>(ei);

    auto ggrid = [](int ncol) { return dim3((unsigned)((ncol + 63) / 64), Nn / 128); };

    // encoder
    k_gemm<<<ggrid(256), 256>>>(x, Wg0, nullptr, t, 38, 256, 0, nullptr);
    k_agg<<<Nn, 256>>>(t, bg0, a, 256, 1, nullptr, nullptr);
    k_gemm<<<ggrid(128), 256>>>(a, Wg1, nullptr, t, 256, 128, 0, nullptr);
    k_agg<<<Nn, 128>>>(t, bg1, a, 128, 1, nullptr, nullptr);
    k_gemm<<<ggrid(64), 256>>>(a, Wg2, nullptr, t, 128, 64, 0, nullptr);
    k_agg<<<Nn, 64>>>(t, bg2, z, 64, 1, bat, zg);   // fused per-graph max pool

    // decoder
    k_gemm<<<ggrid(128), 256>>>(z, Wd0, bd0, a, 64, 128, 1, nullptr);
    k_gemm<<<ggrid(256), 256>>>(a, Wd1, bd1, t, 128, 256, 1, nullptr);
    k_gemm<<<ggrid(38), 256>>>(t, Wd2, bd2, xr, 256, 38, 0, nullptr);

    // edge predictor logits -> fused bf16 split (Lb)
    k_gemm<<<ggrid(64), 256>>>(z, We, be, nullptr, 64, 64, 0, Lb);

    // tensor-core adjacency, triangular grid
    cudaFuncSetAttribute(k_adj_mma, cudaFuncAttributeMaxDynamicSharedMemorySize, ADJ_SMEM);
    k_adj_mma<<<8256, 256, ADJ_SMEM>>>(Lb, adj);
}

// round 5
// speedup vs baseline: 1.7795x; 1.3885x over previous
#include <cuda_runtime.h>
#include <cuda_bf16.h>
#include <cstdint>

#define Nn 16384
#define Ee 262144
#define Gg 128

// ---------------- scratch (no allocations allowed) ----------------
__device__ float g_t[Nn * 256];     // transform output / bf16-split matrix (aliased)
__device__ float g_a[Nn * 256];     // activations
__device__ int   g_deg[Nn];
__device__ float g_inv[Nn];
__device__ int   g_ptr[Nn + 1];
__device__ int   g_fill[Nn];
__device__ int   g_src[Ee];
__device__ float g_w[Ee];

typedef unsigned long long ull;

#define FMA2(c, a, b) asm("fma.rn.f32x2 %0, %1, %2, %0;" : "+l"(c) : "l"(a), "l"(b))
#define DUP2(o, x)    asm("mov.b64 %0, {%1, %1};" : "=l"(o) : "f"(x))
#define PK2(o, x, y)  asm("mov.b64 %0, {%1, %2};" : "=l"(o) : "f"(x), "f"(y))
#define UPK2(x, y, c) asm("mov.b64 {%0, %1}, %2;" : "=f"(x), "=f"(y) : "l"(c))

__device__ __forceinline__ float sigf(float x) {
    return __fdividef(1.0f, 1.0f + __expf(-x));
}

__device__ __forceinline__ uint32_t smem_u32(const void* p) {
    uint32_t a;
    asm("{ .reg .u64 t; cvta.to.shared.u64 t, %1; cvt.u32.u64 %0, t; }" : "=r"(a) : "l"(p));
    return a;
}

__device__ __forceinline__ void ldsm_x4(uint32_t addr, uint32_t* r) {
    asm volatile("ldmatrix.sync.aligned.m8n8.x4.shared.b16 {%0,%1,%2,%3}, [%4];"
        : "=r"(r[0]), "=r"(r[1]), "=r"(r[2]), "=r"(r[3]) : "r"(addr));
}

__device__ __forceinline__ void mma_bf16(float* c, const uint32_t* a, const uint32_t* b) {
    asm volatile("mma.sync.aligned.m16n8k16.row.col.f32.bf16.bf16.f32 "
        "{%0,%1,%2,%3}, {%4,%5,%6,%7}, {%8,%9}, {%0,%1,%2,%3};"
        : "+f"(c[0]), "+f"(c[1]), "+f"(c[2]), "+f"(c[3])
        : "r"(a[0]), "r"(a[1]), "r"(a[2]), "r"(a[3]), "r"(b[0]), "r"(b[1]));
}

// ---------------- graph preprocessing ----------------
__global__ void k_init_deg() {
    int i = blockIdx.x * blockDim.x + threadIdx.x;
    if (i < Nn) g_deg[i] = 1;  // self loop
}

__global__ void k_hist(const int* __restrict__ ei) {
    int e = blockIdx.x * blockDim.x + threadIdx.x;
    if (e < Ee) atomicAdd(&g_deg[ei[Ee + e]], 1);
}

__global__ void k_inv(float* __restrict__ zg) {
    int i = blockIdx.x * blockDim.x + threadIdx.x;
    if (i < Nn) {
        g_inv[i] = rsqrtf((float)g_deg[i]);
        g_fill[i] = 0;
    }
    if (i < Gg * 64) zg[i] = 0.0f;   // zero pooled output (fused)
}

__global__ void k_scan() {  // exclusive prefix over (deg-1), warp-shfl, int4 I/O
    __shared__ int wsum[32];
    int tid = threadIdx.x, lane = tid & 31, wid = tid >> 5;
    const int4* dp = (const int4*)g_deg;
    int4 d4[4];
#pragma unroll
    for (int i = 0; i < 4; i++) d4[i] = dp[tid * 4 + i];
    int loc[16];
#pragma unroll
    for (int i = 0; i < 4; i++) {
        loc[4 * i + 0] = d4[i].x - 1;
        loc[4 * i + 1] = d4[i].y - 1;
        loc[4 * i + 2] = d4[i].z - 1;
        loc[4 * i + 3] = d4[i].w - 1;
    }
    int s = 0;
#pragma unroll
    for (int i = 0; i < 16; i++) s += loc[i];
    int inc = s;
#pragma unroll
    for (int off = 1; off < 32; off <<= 1) {
        int v = __shfl_up_sync(0xFFFFFFFF, inc, off);
        if (lane >= off) inc += v;
    }
    if (lane == 31) wsum[wid] = inc;
    __syncthreads();
    if (wid == 0) {
        int v = wsum[lane];
#pragma unroll
        for (int off = 1; off < 32; off <<= 1) {
            int u = __shfl_up_sync(0xFFFFFFFF, v, off);
            if (lane >= off) v += u;
        }
        wsum[lane] = v;
    }
    __syncthreads();
    int ex = (wid ? wsum[wid - 1] : 0) + inc - s;
    int4* pp = (int4*)g_ptr;
#pragma unroll
    for (int i = 0; i < 4; i++) {
        int4 o;
        o.x = ex; ex += loc[4 * i + 0];
        o.y = ex; ex += loc[4 * i + 1];
        o.z = ex; ex += loc[4 * i + 2];
        o.w = ex; ex += loc[4 * i + 3];
        pp[tid * 4 + i] = o;
    }
    if (tid == 1023) g_ptr[Nn] = ex;
}

__global__ void k_scatter(const int* __restrict__ ei) {
    int e = blockIdx.x * blockDim.x + threadIdx.x;
    if (e >= Ee) return;
    int s = ei[e];
    int d = ei[Ee + e];
    int k = atomicAdd(&g_fill[d], 1);
    int idx = g_ptr[d] + k;
    g_src[idx] = s;
    g_w[idx] = g_inv[s] * g_inv[d];
}

// ---------------- GCN aggregate (optionally fused zg max pool) ----------------
__global__ void k_agg(const float* __restrict__ t, const float* __restrict__ bias,
                      float* __restrict__ out, int d, int relu,
                      const int* __restrict__ batch, float* __restrict__ zg) {
    int v = blockIdx.x;
    int f = threadIdx.x;
    float iv = g_inv[v];
    float acc = iv * iv * t[(size_t)v * d + f];
    int e0 = g_ptr[v], e1 = g_ptr[v + 1];
    int e = e0;
    for (; e + 8 <= e1; e += 8) {
        float p = 0.0f, q = 0.0f;
#pragma unroll
        for (int u = 0; u < 8; u += 2) {
            int s0 = g_src[e + u], s1 = g_src[e + u + 1];
            float w0 = g_w[e + u], w1 = g_w[e + u + 1];
            p += w0 * t[(size_t)s0 * d + f];
            q += w1 * t[(size_t)s1 * d + f];
        }
        acc += p + q;
    }
    for (; e + 4 <= e1; e += 4) {
        int s0 = g_src[e], s1 = g_src[e + 1], s2 = g_src[e + 2], s3 = g_src[e + 3];
        float w0 = g_w[e], w1 = g_w[e + 1], w2 = g_w[e + 2], w3 = g_w[e + 3];
        acc += w0 * t[(size_t)s0 * d + f];
        acc += w1 * t[(size_t)s1 * d + f];
        acc += w2 * t[(size_t)s2 * d + f];
        acc += w3 * t[(size_t)s3 * d + f];
    }
    for (; e < e1; e++) acc += g_w[e] * t[(size_t)g_src[e] * d + f];
    acc += bias[f];
    if (relu) acc = fmaxf(acc, 0.0f);
    out[(size_t)v * d + f] = acc;
    if (zg) atomicMax((int*)&zg[batch[v] * 64 + f], __float_as_int(acc));
}

// ---------------- generic thin GEMM (k-major A panel, vector broadcast loads) ----------------
__global__ __launch_bounds__(256) void k_gemm(
    const float* __restrict__ A, const float* __restrict__ W,
    const float* __restrict__ bias, float* __restrict__ C,
    int K, int Ncol, int relu, __nv_bfloat16* __restrict__ splitOut)
{
    __shared__ __align__(16) float As[16 * 132];   // [k][m], stride 132
    __shared__ __align__(16) float Bs[16 * 64];
    int tid = threadIdx.x;
    int tx = tid & 15, ty = tid >> 4;
    int m0 = blockIdx.y * 128, n0 = blockIdx.x * 64;

    ull c2[4][4];
#pragma unroll
    for (int p = 0; p < 4; p++)
#pragma unroll
        for (int j = 0; j < 4; j++) c2[p][j] = 0ULL;

    for (int kb = 0; kb < K; kb += 16) {
#pragma unroll
        for (int q = 0; q < 8; q++) {
            int li = q * 256 + tid;
            int r = li >> 4, kk = li & 15, kg = kb + kk;
            As[kk * 132 + r] = (kg < K) ? A[(size_t)(m0 + r) * K + kg] : 0.0f;
        }
#pragma unroll
        for (int q = 0; q < 4; q++) {
            int li = q * 256 + tid;
            int kk = li >> 6, n = li & 63, kg = kb + kk;
            Bs[kk * 64 + n] = (kg < K && n0 + n < Ncol) ? W[(size_t)kg * Ncol + n0 + n] : 0.0f;
        }
        __syncthreads();
#pragma unroll
        for (int kk = 0; kk < 16; kk++) {
            float4 bv = *(const float4*)&Bs[kk * 64 + tx * 4];
            float4 a0 = *(const float4*)&As[kk * 132 + ty * 8];
            float4 a1 = *(const float4*)&As[kk * 132 + ty * 8 + 4];
            ull a2[4], bd[4];
            PK2(a2[0], a0.x, a0.y); PK2(a2[1], a0.z, a0.w);
            PK2(a2[2], a1.x, a1.y); PK2(a2[3], a1.z, a1.w);
            DUP2(bd[0], bv.x); DUP2(bd[1], bv.y); DUP2(bd[2], bv.z); DUP2(bd[3], bv.w);
#pragma unroll
            for (int p = 0; p < 4; p++)
#pragma unroll
                for (int j = 0; j < 4; j++) FMA2(c2[p][j], a2[p], bd[j]);
        }
        __syncthreads();
    }

#pragma unroll
    for (int p = 0; p < 4; p++) {
        int r0 = m0 + ty * 8 + 2 * p;
#pragma unroll
        for (int j = 0; j < 4; j++) {
            int col = n0 + tx * 4 + j;
            if (col < Ncol) {
                float lo, hi;
                UPK2(lo, hi, c2[p][j]);
                float bj = bias ? bias[col] : 0.0f;
                lo += bj; hi += bj;
                if (relu) { lo = fmaxf(lo, 0.0f); hi = fmaxf(hi, 0.0f); }
                if (splitOut) {   // Ncol==64: write bf16 split rows [hi64|lo64]
                    __nv_bfloat16 h0 = __float2bfloat16(lo);
                    __nv_bfloat16 h1 = __float2bfloat16(hi);
                    splitOut[(size_t)r0 * 128 + col] = h0;
                    splitOut[(size_t)r0 * 128 + 64 + col] = __float2bfloat16(lo - __bfloat162float(h0));
                    splitOut[(size_t)(r0 + 1) * 128 + col] = h1;
                    splitOut[(size_t)(r0 + 1) * 128 + 64 + col] = __float2bfloat16(hi - __bfloat162float(h1));
                } else {
                    C[(size_t)r0 * Ncol + col] = lo;
                    C[(size_t)(r0 + 1) * Ncol + col] = hi;
                }
            }
        }
    }
}

// ---------------- adjacency via mma.sync bf16: C = sigmoid(Lb @ Lb^T) ----------------
// Triangular 1D grid. 128x128 tile, 8 warps (2x4), warp tile m64n32, K=128.
// Epilogue: normal orientation direct STG.64 from fragments (32B sectors);
// mirror via transposed smem staging [col][r], stride 132 (all accesses conflict-free).
#define ADJ_SMEM (128 * 132 * 4)

__global__ __launch_bounds__(256) void k_adj_mma(const __nv_bfloat16* __restrict__ Lb,
                                                 float* __restrict__ C) {
    int ti = blockIdx.x;
    int p = (int)((sqrtf(8.0f * ti + 1.0f) - 1.0f) * 0.5f);
    while ((p + 1) * (p + 2) / 2 <= ti) p++;
    while (p * (p + 1) / 2 > ti) p--;
    int bx = p, by = ti - p * (p + 1) / 2;

    extern __shared__ __align__(16) char smem[];
    char* smA = smem;            // 128 rows x 256B
    char* smB = smem + 32768;
    int tid = threadIdx.x;
    int w = tid >> 5, l = tid & 31;
    int wm = w & 1, wn = w >> 1;        // warp grid 2 (M) x 4 (N)
    int gi0 = by * 128, gj0 = bx * 128;
    bool diag = (bx == by);

    // ---- panel loads: coalesced uint4, XOR-swizzled store
    {
        const uint4* A4 = (const uint4*)(Lb + (size_t)gi0 * 128);
        const uint4* B4 = (const uint4*)(Lb + (size_t)gj0 * 128);
        int c = tid & 15;
#pragma unroll
        for (int it = 0; it < 8; it++) {
            int r = (tid >> 4) + it * 16;
            int swz = c ^ (r & 7);
            *(uint4*)(smA + r * 256 + swz * 16) = A4[r * 16 + c];
            if (!diag) *(uint4*)(smB + r * 256 + swz * 16) = B4[r * 16 + c];
        }
    }
    __syncthreads();

    uint32_t aA = smem_u32(smA);
    uint32_t aB = diag ? aA : smem_u32(smB);

    float acc[4][4][4];
#pragma unroll
    for (int mi = 0; mi < 4; mi++)
#pragma unroll
        for (int nj = 0; nj < 4; nj++)
#pragma unroll
            for (int q = 0; q < 4; q++) acc[mi][nj][q] = 0.0f;

#pragma unroll
    for (int s = 0; s < 8; s++) {
        uint32_t af[4][4], bf[2][4];
#pragma unroll
        for (int mi = 0; mi < 4; mi++) {
            int row = wm * 64 + mi * 16 + (l & 15);
            int c = (s * 2 + (l >> 4)) ^ (row & 7);
            ldsm_x4(aA + row * 256 + c * 16, af[mi]);
        }
#pragma unroll
        for (int njp = 0; njp < 2; njp++) {
            int n = wn * 32 + njp * 16 + (l & 7) + ((l >> 4) << 3);
            int c = (s * 2 + ((l >> 3) & 1)) ^ (n & 7);
            ldsm_x4(aB + n * 256 + c * 16, bf[njp]);
        }
#pragma unroll
        for (int mi = 0; mi < 4; mi++)
#pragma unroll
            for (int nj = 0; nj < 4; nj++)
                mma_bf16(acc[mi][nj], af[mi], &bf[nj >> 1][(nj & 1) * 2]);
    }

    __syncthreads();  // panels dead; smem reused as transposed staging tile

    float* tileT = (float*)smem;   // [col][r], stride 132
    const size_t NN = (size_t)Nn;

    // sigmoid + direct normal stores (STG.64, 32B sectors) + transposed staging
#pragma unroll
    for (int mi = 0; mi < 4; mi++) {
#pragma unroll
        for (int h = 0; h < 2; h++) {
            int r = wm * 64 + mi * 16 + h * 8 + (l >> 2);
#pragma unroll
            for (int nj = 0; nj < 4; nj++) {
                int cb = wn * 32 + nj * 8 + 2 * (l & 3);
                float v0 = sigf(acc[mi][nj][2 * h]);
                float v1 = sigf(acc[mi][nj][2 * h + 1]);
                *(float2*)&C[(size_t)(gi0 + r) * NN + gj0 + cb] = make_float2(v0, v1);
                if (!diag) {
                    tileT[cb * 132 + r] = v0;
                    tileT[(cb + 1) * 132 + r] = v1;
                }
            }
        }
    }

    // mirror: coalesced float4 rows of C^T from transposed staging
    if (!diag) {
        __syncthreads();
#pragma unroll
        for (int it = 0; it < 16; it++) {
            int idx = it * 256 + tid;
            int colT = idx >> 5, r4 = idx & 31;
            float4 v = *(float4*)&tileT[colT * 132 + r4 * 4];
            *(float4*)&C[(size_t)(gj0 + colT) * NN + gi0 + r4 * 4] = v;
        }
    }
}

// ---------------- launch ----------------
extern "C" void kernel_launch(void* const* d_in, const int* in_sizes, int n_in,
                              void* d_out, int out_size) {
    const float* x   = (const float*)d_in[0];
    const int*   ei  = (const int*)d_in[1];
    const int*   bat = (const int*)d_in[2];
    const float* Wg0 = (const float*)d_in[3];
    const float* bg0 = (const float*)d_in[4];
    const float* Wg1 = (const float*)d_in[5];
    const float* bg1 = (const float*)d_in[6];
    const float* Wg2 = (const float*)d_in[7];
    const float* bg2 = (const float*)d_in[8];
    const float* Wd0 = (const float*)d_in[9];
    const float* bd0 = (const float*)d_in[10];
    const float* Wd1 = (const float*)d_in[11];
    const float* bd1 = (const float*)d_in[12];
    const float* Wd2 = (const float*)d_in[13];
    const float* bd2 = (const float*)d_in[14];
    const float* We  = (const float*)d_in[15];
    const float* be  = (const float*)d_in[16];

    float* out = (float*)d_out;
    float* z   = out;                          // [N,64]
    float* zg  = out + (size_t)Nn * 64;        // [G,64]
    float* xr  = zg + (size_t)Gg * 64;         // [N,38]
    float* adj = xr + (size_t)Nn * 38;         // [N,N]

    float *t, *a;
    {
        void* p;
        cudaGetSymbolAddress(&p, g_t); t = (float*)p;
        cudaGetSymbolAddress(&p, g_a); a = (float*)p;
    }
    __nv_bfloat16* Lb = (__nv_bfloat16*)t;     // alias (t dead by split time)

    // GCN normalization + CSR build
    k_init_deg<<<64, 256>>>();
    k_hist<<<Ee / 256, 256>>>(ei);
    k_inv<<<64, 256>>>(zg);
    k_scan<<<1, 1024>>>();
    k_scatter<<<Ee / 256, 256>>>(ei);

    auto ggrid = [](int ncol) { return dim3((unsigned)((ncol + 63) / 64), Nn / 128); };

    // encoder
    k_gemm<<<ggrid(256), 256>>>(x, Wg0, nullptr, t, 38, 256, 0, nullptr);
    k_agg<<<Nn, 256>>>(t, bg0, a, 256, 1, nullptr, nullptr);
    k_gemm<<<ggrid(128), 256>>>(a, Wg1, nullptr, t, 256, 128, 0, nullptr);
    k_agg<<<Nn, 128>>>(t, bg1, a, 128, 1, nullptr, nullptr);
    k_gemm<<<ggrid(64), 256>>>(a, Wg2, nullptr, t, 128, 64, 0, nullptr);
    k_agg<<<Nn, 64>>>(t, bg2, z, 64, 1, bat, zg);   // fused per-graph max pool

    // decoder
    k_gemm<<<ggrid(128), 256>>>(z, Wd0, bd0, a, 64, 128, 1, nullptr);
    k_gemm<<<ggrid(256), 256>>>(a, Wd1, bd1, t, 128, 256, 1, nullptr);
    k_gemm<<<ggrid(38), 256>>>(t, Wd2, bd2, xr, 256, 38, 0, nullptr);

    // edge predictor logits -> fused bf16 split (Lb)
    k_gemm<<<ggrid(64), 256>>>(z, We, be, nullptr, 64, 64, 0, Lb);

    // tensor-core adjacency, triangular grid
    cudaFuncSetAttribute(k_adj_mma, cudaFuncAttributeMaxDynamicSharedMemorySize, ADJ_SMEM);
    k_adj_mma<<<8256, 256, ADJ_SMEM>>>(Lb, adj);
}

// round 6
// speedup vs baseline: 1.9149x; 1.0761x over previous
#include <cuda_runtime.h>
#include <cuda_bf16.h>
#include <cstdint>

#define Nn 16384
#define Ee 262144
#define Gg 128

// ---------------- scratch (no allocations allowed) ----------------
__device__ float g_t[Nn * 256];     // transform output / bf16-split matrix (aliased)
__device__ float g_a[Nn * 256];     // activations
__device__ int   g_deg[Nn];
__device__ float g_inv[Nn];
__device__ int   g_ptr[Nn + 1];
__device__ int   g_fill[Nn];
__device__ int   g_src[Ee];
__device__ float g_w[Ee];

typedef unsigned long long ull;

#define FMA2(c, a, b) asm("fma.rn.f32x2 %0, %1, %2, %0;" : "+l"(c) : "l"(a), "l"(b))
#define DUP2(o, x)    asm("mov.b64 %0, {%1, %1};" : "=l"(o) : "f"(x))
#define PK2(o, x, y)  asm("mov.b64 %0, {%1, %2};" : "=l"(o) : "f"(x), "f"(y))
#define UPK2(x, y, c) asm("mov.b64 {%0, %1}, %2;" : "=f"(x), "=f"(y) : "l"(c))

__device__ __forceinline__ float sigf(float x) {
    return __fdividef(1.0f, 1.0f + __expf(-x));
}

__device__ __forceinline__ uint32_t smem_u32(const void* p) {
    uint32_t a;
    asm("{ .reg .u64 t; cvta.to.shared.u64 t, %1; cvt.u32.u64 %0, t; }" : "=r"(a) : "l"(p));
    return a;
}

__device__ __forceinline__ void ldsm_x4(uint32_t addr, uint32_t* r) {
    asm volatile("ldmatrix.sync.aligned.m8n8.x4.shared.b16 {%0,%1,%2,%3}, [%4];"
        : "=r"(r[0]), "=r"(r[1]), "=r"(r[2]), "=r"(r[3]) : "r"(addr));
}

__device__ __forceinline__ void mma_bf16(float* c, const uint32_t* a, const uint32_t* b) {
    asm volatile("mma.sync.aligned.m16n8k16.row.col.f32.bf16.bf16.f32 "
        "{%0,%1,%2,%3}, {%4,%5,%6,%7}, {%8,%9}, {%0,%1,%2,%3};"
        : "+f"(c[0]), "+f"(c[1]), "+f"(c[2]), "+f"(c[3])
        : "r"(a[0]), "r"(a[1]), "r"(a[2]), "r"(a[3]), "r"(b[0]), "r"(b[1]));
}

// ---------------- graph preprocessing ----------------
__global__ void k_init_deg() {
    int i = blockIdx.x * blockDim.x + threadIdx.x;
    if (i < Nn) g_deg[i] = 1;  // self loop
}

__global__ void k_hist(const int* __restrict__ ei) {
    int e = blockIdx.x * blockDim.x + threadIdx.x;
    if (e < Ee) atomicAdd(&g_deg[ei[Ee + e]], 1);
}

__global__ void k_inv(float* __restrict__ zg) {
    int i = blockIdx.x * blockDim.x + threadIdx.x;
    if (i < Nn) {
        g_inv[i] = rsqrtf((float)g_deg[i]);
        g_fill[i] = 0;
    }
    if (i < Gg * 64) zg[i] = 0.0f;   // zero pooled output (fused)
}

__global__ void k_scan() {  // exclusive prefix over (deg-1), warp-shfl, int4 I/O
    __shared__ int wsum[32];
    int tid = threadIdx.x, lane = tid & 31, wid = tid >> 5;
    const int4* dp = (const int4*)g_deg;
    int4 d4[4];
#pragma unroll
    for (int i = 0; i < 4; i++) d4[i] = dp[tid * 4 + i];
    int loc[16];
#pragma unroll
    for (int i = 0; i < 4; i++) {
        loc[4 * i + 0] = d4[i].x - 1;
        loc[4 * i + 1] = d4[i].y - 1;
        loc[4 * i + 2] = d4[i].z - 1;
        loc[4 * i + 3] = d4[i].w - 1;
    }
    int s = 0;
#pragma unroll
    for (int i = 0; i < 16; i++) s += loc[i];
    int inc = s;
#pragma unroll
    for (int off = 1; off < 32; off <<= 1) {
        int v = __shfl_up_sync(0xFFFFFFFF, inc, off);
        if (lane >= off) inc += v;
    }
    if (lane == 31) wsum[wid] = inc;
    __syncthreads();
    if (wid == 0) {
        int v = wsum[lane];
#pragma unroll
        for (int off = 1; off < 32; off <<= 1) {
            int u = __shfl_up_sync(0xFFFFFFFF, v, off);
            if (lane >= off) v += u;
        }
        wsum[lane] = v;
    }
    __syncthreads();
    int ex = (wid ? wsum[wid - 1] : 0) + inc - s;
    int4* pp = (int4*)g_ptr;
#pragma unroll
    for (int i = 0; i < 4; i++) {
        int4 o;
        o.x = ex; ex += loc[4 * i + 0];
        o.y = ex; ex += loc[4 * i + 1];
        o.z = ex; ex += loc[4 * i + 2];
        o.w = ex; ex += loc[4 * i + 3];
        pp[tid * 4 + i] = o;
    }
    if (tid == 1023) g_ptr[Nn] = ex;
}

__global__ void k_scatter(const int* __restrict__ ei) {
    int e = blockIdx.x * blockDim.x + threadIdx.x;
    if (e >= Ee) return;
    int s = ei[e];
    int d = ei[Ee + e];
    int k = atomicAdd(&g_fill[d], 1);
    int idx = g_ptr[d] + k;
    g_src[idx] = s;
    g_w[idx] = g_inv[s] * g_inv[d];
}

// ---------------- GCN aggregate, scalar (pre-transform, no bias/relu) ----------------
__global__ void k_agg_pre(const float* __restrict__ x, float* __restrict__ out, int d) {
    int v = blockIdx.x;
    int f = threadIdx.x;
    if (f >= d) return;
    float iv = g_inv[v];
    float acc = iv * iv * x[(size_t)v * d + f];
    int e0 = g_ptr[v], e1 = g_ptr[v + 1];
    int e = e0;
    for (; e + 8 <= e1; e += 8) {
        float p = 0.0f, q = 0.0f;
#pragma unroll
        for (int u = 0; u < 8; u += 2) {
            int s0 = g_src[e + u], s1 = g_src[e + u + 1];
            float w0 = g_w[e + u], w1 = g_w[e + u + 1];
            p += w0 * x[(size_t)s0 * d + f];
            q += w1 * x[(size_t)s1 * d + f];
        }
        acc += p + q;
    }
    for (; e < e1; e++) acc += g_w[e] * x[(size_t)g_src[e] * d + f];
    out[(size_t)v * d + f] = acc;
}

// ---------------- GCN aggregate, float2 (post-transform, bias+relu, opt zg) ----------------
__global__ void k_agg2(const float2* __restrict__ t, const float* __restrict__ bias,
                       float2* __restrict__ out, int d2,
                       const int* __restrict__ batch, float* __restrict__ zg) {
    int v = blockIdx.x;
    int f = threadIdx.x;   // < d2
    float iv = g_inv[v];
    float2 sv = t[(size_t)v * d2 + f];
    float accx = iv * iv * sv.x, accy = iv * iv * sv.y;
    int e0 = g_ptr[v], e1 = g_ptr[v + 1];
    int e = e0;
    for (; e + 8 <= e1; e += 8) {
#pragma unroll
        for (int u = 0; u < 8; u += 2) {
            int s0 = g_src[e + u], s1 = g_src[e + u + 1];
            float w0 = g_w[e + u], w1 = g_w[e + u + 1];
            float2 t0 = t[(size_t)s0 * d2 + f];
            float2 t1 = t[(size_t)s1 * d2 + f];
            accx += w0 * t0.x; accy += w0 * t0.y;
            accx += w1 * t1.x; accy += w1 * t1.y;
        }
    }
    for (; e < e1; e++) {
        int s = g_src[e];
        float w = g_w[e];
        float2 tv = t[(size_t)s * d2 + f];
        accx += w * tv.x; accy += w * tv.y;
    }
    accx = fmaxf(accx + bias[2 * f], 0.0f);
    accy = fmaxf(accy + bias[2 * f + 1], 0.0f);
    out[(size_t)v * d2 + f] = make_float2(accx, accy);
    if (zg) {
        int b = batch[v];
        atomicMax((int*)&zg[b * 64 + 2 * f], __float_as_int(accx));
        atomicMax((int*)&zg[b * 64 + 2 * f + 1], __float_as_int(accy));
    }
}

// ---------------- generic thin GEMM (k-major A panel, vector broadcast loads) ----------------
__global__ __launch_bounds__(256) void k_gemm(
    const float* __restrict__ A, const float* __restrict__ W,
    const float* __restrict__ bias, float* __restrict__ C,
    int K, int Ncol, int relu, __nv_bfloat16* __restrict__ splitOut)
{
    __shared__ __align__(16) float As[16 * 132];   // [k][m], stride 132
    __shared__ __align__(16) float Bs[16 * 64];
    int tid = threadIdx.x;
    int tx = tid & 15, ty = tid >> 4;
    int m0 = blockIdx.y * 128, n0 = blockIdx.x * 64;

    ull c2[4][4];
#pragma unroll
    for (int p = 0; p < 4; p++)
#pragma unroll
        for (int j = 0; j < 4; j++) c2[p][j] = 0ULL;

    for (int kb = 0; kb < K; kb += 16) {
#pragma unroll
        for (int q = 0; q < 8; q++) {
            int li = q * 256 + tid;
            int r = li >> 4, kk = li & 15, kg = kb + kk;
            As[kk * 132 + r] = (kg < K) ? A[(size_t)(m0 + r) * K + kg] : 0.0f;
        }
#pragma unroll
        for (int q = 0; q < 4; q++) {
            int li = q * 256 + tid;
            int kk = li >> 6, n = li & 63, kg = kb + kk;
            Bs[kk * 64 + n] = (kg < K && n0 + n < Ncol) ? W[(size_t)kg * Ncol + n0 + n] : 0.0f;
        }
        __syncthreads();
#pragma unroll
        for (int kk = 0; kk < 16; kk++) {
            float4 bv = *(const float4*)&Bs[kk * 64 + tx * 4];
            float4 a0 = *(const float4*)&As[kk * 132 + ty * 8];
            float4 a1 = *(const float4*)&As[kk * 132 + ty * 8 + 4];
            ull a2[4], bd[4];
            PK2(a2[0], a0.x, a0.y); PK2(a2[1], a0.z, a0.w);
            PK2(a2[2], a1.x, a1.y); PK2(a2[3], a1.z, a1.w);
            DUP2(bd[0], bv.x); DUP2(bd[1], bv.y); DUP2(bd[2], bv.z); DUP2(bd[3], bv.w);
#pragma unroll
            for (int p = 0; p < 4; p++)
#pragma unroll
                for (int j = 0; j < 4; j++) FMA2(c2[p][j], a2[p], bd[j]);
        }
        __syncthreads();
    }

#pragma unroll
    for (int p = 0; p < 4; p++) {
        int r0 = m0 + ty * 8 + 2 * p;
#pragma unroll
        for (int j = 0; j < 4; j++) {
            int col = n0 + tx * 4 + j;
            if (col < Ncol) {
                float lo, hi;
                UPK2(lo, hi, c2[p][j]);
                float bj = bias ? bias[col] : 0.0f;
                lo += bj; hi += bj;
                if (relu) { lo = fmaxf(lo, 0.0f); hi = fmaxf(hi, 0.0f); }
                if (splitOut) {   // Ncol==64: write bf16 split rows [hi64|lo64]
                    __nv_bfloat16 h0 = __float2bfloat16(lo);
                    __nv_bfloat16 h1 = __float2bfloat16(hi);
                    splitOut[(size_t)r0 * 128 + col] = h0;
                    splitOut[(size_t)r0 * 128 + 64 + col] = __float2bfloat16(lo - __bfloat162float(h0));
                    splitOut[(size_t)(r0 + 1) * 128 + col] = h1;
                    splitOut[(size_t)(r0 + 1) * 128 + 64 + col] = __float2bfloat16(hi - __bfloat162float(h1));
                } else {
                    C[(size_t)r0 * Ncol + col] = lo;
                    C[(size_t)(r0 + 1) * Ncol + col] = hi;
                }
            }
        }
    }
}

// ---------------- adjacency via mma.sync bf16: C = sigmoid(Lb @ Lb^T) ----------------
// Triangular 1D grid. 128x128 tile, 8 warps (2x4), warp tile m64n32, K=128.
// Normal orientation: direct STG.64 (streaming); mirror via transposed smem staging.
#define ADJ_SMEM (128 * 132 * 4)

__global__ __launch_bounds__(256) void k_adj_mma(const __nv_bfloat16* __restrict__ Lb,
                                                 float* __restrict__ C) {
    int ti = blockIdx.x;
    int p = (int)((sqrtf(8.0f * ti + 1.0f) - 1.0f) * 0.5f);
    while ((p + 1) * (p + 2) / 2 <= ti) p++;
    while (p * (p + 1) / 2 > ti) p--;
    int bx = p, by = ti - p * (p + 1) / 2;

    extern __shared__ __align__(16) char smem[];
    char* smA = smem;            // 128 rows x 256B
    char* smB = smem + 32768;
    int tid = threadIdx.x;
    int w = tid >> 5, l = tid & 31;
    int wm = w & 1, wn = w >> 1;        // warp grid 2 (M) x 4 (N)
    int gi0 = by * 128, gj0 = bx * 128;
    bool diag = (bx == by);

    {
        const uint4* A4 = (const uint4*)(Lb + (size_t)gi0 * 128);
        const uint4* B4 = (const uint4*)(Lb + (size_t)gj0 * 128);
        int c = tid & 15;
#pragma unroll
        for (int it = 0; it < 8; it++) {
            int r = (tid >> 4) + it * 16;
            int swz = c ^ (r & 7);
            *(uint4*)(smA + r * 256 + swz * 16) = A4[r * 16 + c];
            if (!diag) *(uint4*)(smB + r * 256 + swz * 16) = B4[r * 16 + c];
        }
    }
    __syncthreads();

    uint32_t aA = smem_u32(smA);
    uint32_t aB = diag ? aA : smem_u32(smB);

    float acc[4][4][4];
#pragma unroll
    for (int mi = 0; mi < 4; mi++)
#pragma unroll
        for (int nj = 0; nj < 4; nj++)
#pragma unroll
            for (int q = 0; q < 4; q++) acc[mi][nj][q] = 0.0f;

#pragma unroll
    for (int s = 0; s < 8; s++) {
        uint32_t af[4][4], bf[2][4];
#pragma unroll
        for (int mi = 0; mi < 4; mi++) {
            int row = wm * 64 + mi * 16 + (l & 15);
            int c = (s * 2 + (l >> 4)) ^ (row & 7);
            ldsm_x4(aA + row * 256 + c * 16, af[mi]);
        }
#pragma unroll
        for (int njp = 0; njp < 2; njp++) {
            int n = wn * 32 + njp * 16 + (l & 7) + ((l >> 4) << 3);
            int c = (s * 2 + ((l >> 3) & 1)) ^ (n & 7);
            ldsm_x4(aB + n * 256 + c * 16, bf[njp]);
        }
#pragma unroll
        for (int mi = 0; mi < 4; mi++)
#pragma unroll
            for (int nj = 0; nj < 4; nj++)
                mma_bf16(acc[mi][nj], af[mi], &bf[nj >> 1][(nj & 1) * 2]);
    }

    __syncthreads();  // panels dead; smem reused as transposed staging tile

    float* tileT = (float*)smem;   // [col][r], stride 132
    const size_t NN = (size_t)Nn;

#pragma unroll
    for (int mi = 0; mi < 4; mi++) {
#pragma unroll
        for (int h = 0; h < 2; h++) {
            int r = wm * 64 + mi * 16 + h * 8 + (l >> 2);
#pragma unroll
            for (int nj = 0; nj < 4; nj++) {
                int cb = wn * 32 + nj * 8 + 2 * (l & 3);
                float v0 = sigf(acc[mi][nj][2 * h]);
                float v1 = sigf(acc[mi][nj][2 * h + 1]);
                __stwt((float2*)&C[(size_t)(gi0 + r) * NN + gj0 + cb], make_float2(v0, v1));
                if (!diag) {
                    tileT[cb * 132 + r] = v0;
                    tileT[(cb + 1) * 132 + r] = v1;
                }
            }
        }
    }

    if (!diag) {
        __syncthreads();
#pragma unroll
        for (int it = 0; it < 16; it++) {
            int idx = it * 256 + tid;
            int colT = idx >> 5, r4 = idx & 31;
            float4 v = *(float4*)&tileT[colT * 132 + r4 * 4];
            __stwt((float4*)&C[(size_t)(gj0 + colT) * NN + gi0 + r4 * 4], v);
        }
    }
}

// ---------------- launch ----------------
extern "C" void kernel_launch(void* const* d_in, const int* in_sizes, int n_in,
                              void* d_out, int out_size) {
    const float* x   = (const float*)d_in[0];
    const int*   ei  = (const int*)d_in[1];
    const int*   bat = (const int*)d_in[2];
    const float* Wg0 = (const float*)d_in[3];
    const float* bg0 = (const float*)d_in[4];
    const float* Wg1 = (const float*)d_in[5];
    const float* bg1 = (const float*)d_in[6];
    const float* Wg2 = (const float*)d_in[7];
    const float* bg2 = (const float*)d_in[8];
    const float* Wd0 = (const float*)d_in[9];
    const float* bd0 = (const float*)d_in[10];
    const float* Wd1 = (const float*)d_in[11];
    const float* bd1 = (const float*)d_in[12];
    const float* Wd2 = (const float*)d_in[13];
    const float* bd2 = (const float*)d_in[14];
    const float* We  = (const float*)d_in[15];
    const float* be  = (const float*)d_in[16];

    float* out = (float*)d_out;
    float* z   = out;                          // [N,64]
    float* zg  = out + (size_t)Nn * 64;        // [G,64]
    float* xr  = zg + (size_t)Gg * 64;         // [N,38]
    float* adj = xr + (size_t)Nn * 38;         // [N,N]

    float *t, *a;
    {
        void* p;
        cudaGetSymbolAddress(&p, g_t); t = (float*)p;
        cudaGetSymbolAddress(&p, g_a); a = (float*)p;
    }
    __nv_bfloat16* Lb = (__nv_bfloat16*)t;     // alias (t dead by split time)

    // GCN normalization + CSR build
    k_init_deg<<<64, 256>>>();
    k_hist<<<Ee / 256, 256>>>(ei);
    k_inv<<<64, 256>>>(zg);
    k_scan<<<1, 1024>>>();
    k_scatter<<<Ee / 256, 256>>>(ei);

    auto ggrid = [](int ncol) { return dim3((unsigned)((ncol + 63) / 64), Nn / 128); };

    // encoder — layer 1: aggregate FIRST at d=38 (agg is linear), then fused GEMM+bias+relu
    k_agg_pre<<<Nn, 64>>>(x, t, 38);
    k_gemm<<<ggrid(256), 256>>>(t, Wg0, bg0, a, 38, 256, 1, nullptr);
    // layer 2: transform 256->128, aggregate at 128
    k_gemm<<<ggrid(128), 256>>>(a, Wg1, nullptr, t, 256, 128, 0, nullptr);
    k_agg2<<<Nn, 64>>>((const float2*)t, bg1, (float2*)a, 64, nullptr, nullptr);
    // layer 3: transform 128->64, aggregate at 64 (fused zg max pool)
    k_gemm<<<ggrid(64), 256>>>(a, Wg2, nullptr, t, 128, 64, 0, nullptr);
    k_agg2<<<Nn, 32>>>((const float2*)t, bg2, (float2*)z, 32, bat, zg);

    // decoder
    k_gemm<<<ggrid(128), 256>>>(z, Wd0, bd0, a, 64, 128, 1, nullptr);
    k_gemm<<<ggrid(256), 256>>>(a, Wd1, bd1, t, 128, 256, 1, nullptr);
    k_gemm<<<ggrid(38), 256>>>(t, Wd2, bd2, xr, 256, 38, 0, nullptr);

    // edge predictor logits -> fused bf16 split (Lb)
    k_gemm<<<ggrid(64), 256>>>(z, We, be, nullptr, 64, 64, 0, Lb);

    // tensor-core adjacency, triangular grid
    cudaFuncSetAttribute(k_adj_mma, cudaFuncAttributeMaxDynamicSharedMemorySize, ADJ_SMEM);
    k_adj_mma<<<8256, 256, ADJ_SMEM>>>(Lb, adj);
}